// round 7
// baseline (speedup 1.0000x reference)
#include <cuda_runtime.h>
#include <math.h>

#define N3 (128*128*128)
#define NZH 65                       // Hermitian half length along z
#define KLINES (128*65)              // 8320 k-space lines for y/x passes
#define NBINS 4096                   // 16x16x16 bins of 8^3 cells
#define MAXATOMS 262144

__device__ float2 d_kmesh[128*128*NZH];  // half-spectrum mesh (8.5 MB)
__device__ float  d_rho[N3];             // dense real mesh (8 MB)
__device__ int    d_binCnt[NBINS];
__device__ int    d_binOff[NBINS];       // running cursor for reorder
__device__ float4 d_atoms[MAXATOMS];     // sorted {x,y,z,charge}
__device__ int    d_origIdx[MAXATOMS];

// ---------------------------------------------------------------------------
__device__ __forceinline__ float2 cadd(float2 a, float2 b){ return make_float2(a.x+b.x, a.y+b.y); }
__device__ __forceinline__ float2 csub(float2 a, float2 b){ return make_float2(a.x-b.x, a.y-b.y); }
__device__ __forceinline__ float2 cmul(float2 a, float2 w){ return make_float2(a.x*w.x-a.y*w.y, a.x*w.y+a.y*w.x); }

__device__ __forceinline__ void inv3x3(const float* __restrict__ cell,
                                       float inv[9], float& det) {
    float a = __ldg(cell+0), b = __ldg(cell+1), c = __ldg(cell+2);
    float d = __ldg(cell+3), e = __ldg(cell+4), f = __ldg(cell+5);
    float g = __ldg(cell+6), h = __ldg(cell+7), i = __ldg(cell+8);
    float C00 =  (e*i - f*h), C01 = -(d*i - f*g), C02 =  (d*h - e*g);
    float C10 = -(b*i - c*h), C11 =  (a*i - c*g), C12 = -(a*h - b*g);
    float C20 =  (b*f - c*e), C21 = -(a*f - c*d), C22 =  (a*e - b*d);
    det = a*C00 + b*C01 + c*C02;
    float idet = 1.0f / det;
    inv[0]=C00*idet; inv[1]=C10*idet; inv[2]=C20*idet;
    inv[3]=C01*idet; inv[4]=C11*idet; inv[5]=C21*idet;
    inv[6]=C02*idet; inv[7]=C12*idet; inv[8]=C22*idet;
}

__device__ __forceinline__ void frac_idx(const float* __restrict__ cell,
                                         float p0, float p1, float p2,
                                         float& r0, float& r1, float& r2,
                                         int& i0, int& i1, int& i2) {
    float inv[9]; float det;
    inv3x3(cell, inv, det);
    r0 = (p0*inv[0] + p1*inv[3] + p2*inv[6]) * 128.0f;
    r1 = (p0*inv[1] + p1*inv[4] + p2*inv[7]) * 128.0f;
    r2 = (p0*inv[2] + p1*inv[5] + p2*inv[8]) * 128.0f;
    i0 = __float2int_rd(r0);
    i1 = __float2int_rd(r1);
    i2 = __float2int_rd(r2);
}

// ---------------------------------------------------------------------------
__global__ void k_zero() {
    int i = blockIdx.x * blockDim.x + threadIdx.x;   // 524288 float4s (8 MB)
    ((float4*)d_rho)[i] = make_float4(0.f, 0.f, 0.f, 0.f);
    if (blockIdx.x == 0) {
        #pragma unroll
        for (int t = 0; t < 16; t++)
            d_binCnt[threadIdx.x * 16 + t] = 0;
    }
}

// ---------------------------------------------------------------------------
// binning: histogram -> scan -> reorder
// ---------------------------------------------------------------------------
__global__ void k_bin(const float* __restrict__ cell,
                      const float* __restrict__ pos, int n) {
    int a = blockIdx.x * blockDim.x + threadIdx.x;
    if (a >= n) return;
    float r0, r1, r2; int i0, i1, i2;
    frac_idx(cell, pos[3*a], pos[3*a+1], pos[3*a+2], r0, r1, r2, i0, i1, i2);
    int bin = (((i0 & 127) >> 3) << 8) | (((i1 & 127) >> 3) << 4) | ((i2 & 127) >> 3);
    atomicAdd(&d_binCnt[bin], 1);
}

__global__ void k_scan() {             // 1 block, 1024 threads, 4 bins each
    __shared__ int s[1024];
    int tid = threadIdx.x;
    int v0 = d_binCnt[tid*4+0], v1 = d_binCnt[tid*4+1];
    int v2 = d_binCnt[tid*4+2], v3 = d_binCnt[tid*4+3];
    int mysum = v0 + v1 + v2 + v3;
    s[tid] = mysum;
    __syncthreads();
    for (int off = 1; off < 1024; off <<= 1) {
        int t = (tid >= off) ? s[tid - off] : 0;
        __syncthreads();
        s[tid] += t;
        __syncthreads();
    }
    int e = s[tid] - mysum;
    d_binOff[tid*4+0] = e; e += v0;
    d_binOff[tid*4+1] = e; e += v1;
    d_binOff[tid*4+2] = e; e += v2;
    d_binOff[tid*4+3] = e;
}

__global__ void k_reorder(const float* __restrict__ cell,
                          const float* __restrict__ pos,
                          const float* __restrict__ chg, int n) {
    int a = blockIdx.x * blockDim.x + threadIdx.x;
    if (a >= n) return;
    float p0 = pos[3*a], p1 = pos[3*a+1], p2 = pos[3*a+2];
    float r0, r1, r2; int i0, i1, i2;
    frac_idx(cell, p0, p1, p2, r0, r1, r2, i0, i1, i2);
    int bin = (((i0 & 127) >> 3) << 8) | (((i1 & 127) >> 3) << 4) | ((i2 & 127) >> 3);
    int slot = atomicAdd(&d_binOff[bin], 1);
    d_atoms[slot] = make_float4(p0, p1, p2, chg[a]);
    d_origIdx[slot] = a;
}

// ---------------------------------------------------------------------------
// Radix-4 Stockham stage over 8 lines of 128 (padded stride 129).
// ---------------------------------------------------------------------------
template<int CONJ, int S>
__device__ __forceinline__ void r4_stage(const float2* __restrict__ cur,
                                         float2* __restrict__ nxt,
                                         const float2* __restrict__ tw, int tid) {
    int c = tid >> 5, t = tid & 31;
    int off = c * 129;
    int q  = t & (S - 1);
    int sp = t - q;
    float2 a0 = cur[off + t];
    float2 a1 = cur[off + t + 32];
    float2 a2 = cur[off + t + 64];
    float2 a3 = cur[off + t + 96];
    float2 t02 = cadd(a0, a2), d02 = csub(a0, a2);
    float2 t13 = cadd(a1, a3), d13 = csub(a1, a3);
    float2 y0 = cadd(t02, t13);
    float2 y2 = csub(t02, t13);
    float2 jd;
    if (CONJ) jd = make_float2(-d13.y,  d13.x);
    else      jd = make_float2( d13.y, -d13.x);
    float2 y1 = cadd(d02, jd);
    float2 y3 = csub(d02, jd);
    float2 w1 = tw[sp], w2 = tw[2*sp], w3 = tw[3*sp];
    if (CONJ) { w1.y = -w1.y; w2.y = -w2.y; w3.y = -w3.y; }
    int o = off + t + 3*sp;
    nxt[o]       = y0;
    nxt[o + S]   = cmul(y1, w1);
    nxt[o + 2*S] = cmul(y2, w2);
    nxt[o + 3*S] = cmul(y3, w3);
}

template<int CONJ>
__device__ __forceinline__ void fft_r4_stages(float2* A, float2* B,
                                              const float2* tw, int tid) {
    r4_stage<CONJ, 1 >(A, B, tw, tid); __syncthreads();
    r4_stage<CONJ, 4 >(B, A, tw, tid); __syncthreads();
    r4_stage<CONJ, 16>(A, B, tw, tid); __syncthreads();
}

__device__ __forceinline__ void r2_final_shared(const float2* __restrict__ src,
                                                float2* __restrict__ dst, int tid) {
    #pragma unroll
    for (int e = tid; e < 512; e += 256) {
        int c = e >> 6, t = e & 63;
        float2 a = src[c * 129 + t], b = src[c * 129 + t + 64];
        dst[c * 129 + t]      = cadd(a, b);
        dst[c * 129 + t + 64] = csub(a, b);
    }
}

__device__ __forceinline__ void init_tw(float2* tw, int tid) {
    if (tid < 128) {
        float s, c;
        sincospif((float)tid * (1.0f / 64.0f), &s, &c);
        tw[tid] = make_float2(c, -s);
    }
}

// ---------------------------------------------------------------------------
__global__ void k_fft_z_fwd() {
    __shared__ float2 bufA[8 * 129];
    __shared__ float2 bufB[8 * 129];
    __shared__ float2 tw[128];
    int tid = threadIdx.x;
    int rl0 = blockIdx.x * 16;
    init_tw(tw, tid);
    const float* rp = d_rho + rl0 * 128;
    #pragma unroll
    for (int e = tid; e < 1024; e += 256) {
        int c = e >> 7, l = e & 127;
        bufA[c * 129 + l] = make_float2(rp[(2*c) * 128 + l], rp[(2*c+1) * 128 + l]);
    }
    __syncthreads();
    fft_r4_stages<0>(bufA, bufB, tw, tid);
    r2_final_shared(bufB, bufA, tid);
    __syncthreads();
    for (int e = tid; e < 16 * NZH; e += 256) {
        int rl = e / NZH, k = e - rl * NZH;
        int c = rl >> 1;
        float2 Ck = bufA[c * 129 + k];
        float2 Cm = bufA[c * 129 + ((128 - k) & 127)];
        float2 v;
        if ((rl & 1) == 0)
            v = make_float2(0.5f * (Ck.x + Cm.x), 0.5f * (Ck.y - Cm.y));
        else
            v = make_float2(0.5f * (Ck.y + Cm.y), -0.5f * (Ck.x - Cm.x));
        d_kmesh[(rl0 + rl) * NZH + k] = v;
    }
}

__global__ void k_fft_z_inv() {
    __shared__ float2 bufA[8 * 129];
    __shared__ float2 bufB[8 * 129];
    __shared__ float2 tw[128];
    int tid = threadIdx.x;
    int rl0 = blockIdx.x * 16;
    init_tw(tw, tid);
    for (int e = tid; e < 8 * NZH; e += 256) {
        int c = e / NZH, k = e - c * NZH;
        float2 A = d_kmesh[(rl0 + 2*c)   * NZH + k];
        float2 B = d_kmesh[(rl0 + 2*c+1) * NZH + k];
        bufA[c * 129 + k] = make_float2(A.x - B.y, A.y + B.x);
        if (k >= 1 && k <= 63)
            bufA[c * 129 + 128 - k] = make_float2(A.x + B.y, B.x - A.y);
    }
    __syncthreads();
    fft_r4_stages<1>(bufA, bufB, tw, tid);
    float* rp = d_rho + rl0 * 128;
    #pragma unroll
    for (int e = tid; e < 512; e += 256) {
        int c = e >> 6, l = e & 63;
        float2 a = bufB[c * 129 + l], b = bufB[c * 129 + l + 64];
        float2 su = cadd(a, b), df = csub(a, b);
        rp[(2*c) * 128 + l]        = su.x;
        rp[(2*c+1) * 128 + l]      = su.y;
        rp[(2*c) * 128 + l + 64]   = df.x;
        rp[(2*c+1) * 128 + l + 64] = df.y;
    }
}

template<int CONJ>
__global__ void k_fft_y() {
    __shared__ float2 bufA[8 * 129];
    __shared__ float2 bufB[8 * 129];
    __shared__ float2 tw[128];
    __shared__ int lineBase[8];
    int tid = threadIdx.x;
    init_tw(tw, tid);
    if (tid < 8) {
        int L = blockIdx.x * 8 + tid;
        int x = L / NZH, kz = L - x * NZH;
        lineBase[tid] = x * (128 * NZH) + kz;
    }
    __syncthreads();
    #pragma unroll
    for (int e = tid; e < 1024; e += 256) {
        int c = e & 7, l = e >> 3;
        bufA[c * 129 + l] = d_kmesh[lineBase[c] + l * NZH];
    }
    __syncthreads();
    fft_r4_stages<CONJ>(bufA, bufB, tw, tid);
    #pragma unroll
    for (int e = tid; e < 512; e += 256) {
        int c = e & 7, l = e >> 3;
        float2 a = bufB[c * 129 + l], b = bufB[c * 129 + l + 64];
        d_kmesh[lineBase[c] + l * NZH]        = cadd(a, b);
        d_kmesh[lineBase[c] + (l + 64) * NZH] = csub(a, b);
    }
}

__global__ void k_fft_x_gmul(const float* __restrict__ cell) {
    __shared__ float2 bufA[8 * 129];
    __shared__ float2 bufB[8 * 129];
    __shared__ float2 tw[128];
    __shared__ float mjv[8], mkv[8];
    int tid = threadIdx.x;
    int L0 = blockIdx.x * 8;
    init_tw(tw, tid);
    if (tid < 8) {
        int L = L0 + tid;
        int y = L / NZH, kz = L - y * NZH;
        mjv[tid] = (float)(y - ((y >= 64) ? 128 : 0));
        mkv[tid] = (float)kz;
    }
    float inv[9]; float det;
    inv3x3(cell, inv, det);
    const float TWO_PI = 6.283185307179586f;
    float b0x = TWO_PI*inv[0], b0y = TWO_PI*inv[3], b0z = TWO_PI*inv[6];
    float b1x = TWO_PI*inv[1], b1y = TWO_PI*inv[4], b1z = TWO_PI*inv[7];
    float b2x = TWO_PI*inv[2], b2y = TWO_PI*inv[5], b2z = TWO_PI*inv[8];
    float ivol = 1.0f / fabsf(det);
    __syncthreads();
    #pragma unroll
    for (int e = tid; e < 1024; e += 256) {
        int c = e & 7, l = e >> 3;
        bufA[c * 129 + l] = d_kmesh[L0 + c + l * KLINES];
    }
    __syncthreads();
    fft_r4_stages<0>(bufA, bufB, tw, tid);
    r2_final_shared(bufB, bufA, tid);
    __syncthreads();
    #pragma unroll
    for (int e = tid; e < 1024; e += 256) {
        int c = e >> 7, xk = e & 127;
        float mi = (float)(xk - ((xk >= 64) ? 128 : 0));
        float mj = mjv[c], mk = mkv[c];
        float kx = mi * b0x + mj * b1x + mk * b2x;
        float ky = mi * b0y + mj * b1y + mk * b2y;
        float kz = mi * b0z + mj * b1z + mk * b2z;
        float ksq = kx*kx + ky*ky + kz*kz;
        float g = 0.0f;
        if (ksq != 0.0f)
            g = 12.566370614359172f / ksq * expf(-0.5f * ksq) * ivol;
        float2 v = bufA[c * 129 + xk];
        v.x *= g; v.y *= g;
        bufA[c * 129 + xk] = v;
    }
    __syncthreads();
    fft_r4_stages<1>(bufA, bufB, tw, tid);
    #pragma unroll
    for (int e = tid; e < 512; e += 256) {
        int c = e & 7, l = e >> 3;
        float2 a = bufB[c * 129 + l], b = bufB[c * 129 + l + 64];
        d_kmesh[L0 + c + l * KLINES]        = cadd(a, b);
        d_kmesh[L0 + c + (l + 64) * KLINES] = csub(a, b);
    }
}

// ---------------------------------------------------------------------------
// spline weights + stencil (from sorted float4 atom record)
// ---------------------------------------------------------------------------
__device__ __forceinline__ void spline_w4(float x, float* w) {
    float x2 = x * x, x3 = x2 * x;
    const float s = 1.0f / 48.0f;
    w[0] = ( 1.0f -  6.0f*x + 12.0f*x2 -  8.0f*x3) * s;
    w[1] = (23.0f - 30.0f*x - 12.0f*x2 + 24.0f*x3) * s;
    w[2] = (23.0f + 30.0f*x - 12.0f*x2 - 24.0f*x3) * s;
    w[3] = ( 1.0f +  6.0f*x + 12.0f*x2 +  8.0f*x3) * s;
}

__device__ __forceinline__ int atom_stencil4(
    const float* __restrict__ cell, float4 at,
    float* wx, float* wy, float* wz, int* ix, int* iy)
{
    float r0, r1, r2; int i0, i1, i2;
    frac_idx(cell, at.x, at.y, at.z, r0, r1, r2, i0, i1, i2);
    spline_w4(r0 - (float)i0 - 0.5f, wx);
    spline_w4(r1 - (float)i1 - 0.5f, wy);
    spline_w4(r2 - (float)i2 - 0.5f, wz);
    #pragma unroll
    for (int s = 0; s < 4; s++) {
        ix[s] = (i0 + s - 1 + 128) & 127;
        iy[s] = (i1 + s - 1 + 128) & 127;
    }
    return i2;
}

__device__ __forceinline__ void pad_quads(const float* wz, int off,
                                          float* q0, float* q1) {
    switch (off) {
    case 0: q0[0]=wz[0]; q0[1]=wz[1]; q0[2]=wz[2]; q0[3]=wz[3]; break;
    case 1: q0[1]=wz[0]; q0[2]=wz[1]; q0[3]=wz[2]; q1[0]=wz[3]; break;
    case 2: q0[2]=wz[0]; q0[3]=wz[1]; q1[0]=wz[2]; q1[1]=wz[3]; break;
    default:q0[3]=wz[0]; q1[0]=wz[1]; q1[1]=wz[2]; q1[2]=wz[3]; break;
    }
}

__device__ __forceinline__ void red4(float* p, float a, float b, float c, float d) {
    asm volatile("red.global.add.v4.f32 [%0], {%1, %2, %3, %4};"
                 :: "l"(p), "f"(a), "f"(b), "f"(c), "f"(d) : "memory");
}
__device__ __forceinline__ void red2(float* p, float a, float b) {
    asm volatile("red.global.add.v2.f32 [%0], {%1, %2};"
                 :: "l"(p), "f"(a), "f"(b) : "memory");
}
__device__ __forceinline__ void red1(float* p, float a) {
    asm volatile("red.global.add.f32 [%0], %1;"
                 :: "l"(p), "f"(a) : "memory");
}

// ---------------------------------------------------------------------------
__global__ void k_scatter(const float* __restrict__ cell, int n) {
    int a = blockIdx.x * blockDim.x + threadIdx.x;
    if (a >= n) return;
    float4 at = d_atoms[a];
    float wx[4], wy[4], wz[4];
    int ix[4], iy[4];
    int i2 = atom_stencil4(cell, at, wx, wy, wz, ix, iy);
    float c = at.w;
    int zlo = i2 - 1;
    if (zlo >= 0 && zlo <= 124) {
        int Q0 = zlo & ~3, off = zlo & 3;
        #pragma unroll
        for (int i = 0; i < 4; i++) {
            float cwi = c * wx[i];
            int ox = ix[i] << 14;
            #pragma unroll
            for (int j = 0; j < 4; j++) {
                float s = cwi * wy[j];
                float* p = &d_rho[ox + (iy[j] << 7) + Q0];
                switch (off) {
                case 0:
                    red4(p, s*wz[0], s*wz[1], s*wz[2], s*wz[3]);
                    break;
                case 1:
                    red1(p + 1, s*wz[0]);
                    red2(p + 2, s*wz[1], s*wz[2]);
                    red1(p + 4, s*wz[3]);
                    break;
                case 2:
                    red2(p + 2, s*wz[0], s*wz[1]);
                    red2(p + 4, s*wz[2], s*wz[3]);
                    break;
                default:
                    red1(p + 3, s*wz[0]);
                    red2(p + 4, s*wz[1], s*wz[2]);
                    red1(p + 6, s*wz[3]);
                    break;
                }
            }
        }
    } else {
        int iz[4];
        #pragma unroll
        for (int s = 0; s < 4; s++) iz[s] = (zlo + s + 128) & 127;
        #pragma unroll
        for (int i = 0; i < 4; i++) {
            float cwi = c * wx[i];
            int ox = ix[i] << 14;
            #pragma unroll
            for (int j = 0; j < 4; j++) {
                float cwij = cwi * wy[j];
                int oxy = ox + (iy[j] << 7);
                #pragma unroll
                for (int k = 0; k < 4; k++)
                    red1(&d_rho[oxy + iz[k]], cwij * wz[k]);
            }
        }
    }
}

// ---------------------------------------------------------------------------
__global__ void k_gather(const float* __restrict__ cell,
                         float* __restrict__ out, int n) {
    int a = blockIdx.x * blockDim.x + threadIdx.x;
    if (a >= n) return;
    float4 at = d_atoms[a];
    float wx[4], wy[4], wz[4];
    int ix[4], iy[4];
    int i2 = atom_stencil4(cell, at, wx, wy, wz, ix, iy);
    float sum = 0.0f;
    int zlo = i2 - 1;
    if (zlo >= 0 && zlo <= 124) {
        int Q0 = zlo & ~3, off = zlo & 3;
        float q0[4] = {0,0,0,0}, q1[4] = {0,0,0,0};
        pad_quads(wz, off, q0, q1);
        #pragma unroll
        for (int i = 0; i < 4; i++) {
            float wi = wx[i];
            int ox = ix[i] << 14;
            #pragma unroll
            for (int j = 0; j < 4; j++) {
                const float* p = &d_rho[ox + (iy[j] << 7) + Q0];
                float4 v0 = __ldg((const float4*)p);
                float acc = v0.x*q0[0] + v0.y*q0[1] + v0.z*q0[2] + v0.w*q0[3];
                if (off) {
                    float4 v1 = __ldg((const float4*)(p + 4));
                    acc += v1.x*q1[0] + v1.y*q1[1] + v1.z*q1[2] + v1.w*q1[3];
                }
                sum += wi * wy[j] * acc;
            }
        }
    } else {
        int iz[4];
        #pragma unroll
        for (int s = 0; s < 4; s++) iz[s] = (zlo + s + 128) & 127;
        #pragma unroll
        for (int i = 0; i < 4; i++) {
            float wi = wx[i];
            int ox = ix[i] << 14;
            #pragma unroll
            for (int j = 0; j < 4; j++) {
                int oxy = ox + (iy[j] << 7);
                float acc = 0.0f;
                #pragma unroll
                for (int k = 0; k < 4; k++)
                    acc += wz[k] * d_rho[oxy + iz[k]];
                sum += wi * wy[j] * acc;
            }
        }
    }
    out[d_origIdx[a]] = sum - at.w * 0.7978845608028654f;
}

// ---------------------------------------------------------------------------
extern "C" void kernel_launch(void* const* d_in, const int* in_sizes, int n_in,
                              void* d_out, int out_size) {
    const float* cell = (const float*)d_in[0];
    const float* pos  = (const float*)d_in[1];
    const float* chg  = (const float*)d_in[2];
    float* out = (float*)d_out;
    int n = in_sizes[2];

    int ab = (n + 255) / 256;

    k_zero<<<2048, 256>>>();
    k_bin<<<ab, 256>>>(cell, pos, n);
    k_scan<<<1, 1024>>>();
    k_reorder<<<ab, 256>>>(cell, pos, chg, n);

    k_scatter<<<ab, 256>>>(cell, n);

    k_fft_z_fwd<<<1024, 256>>>();
    k_fft_y<0><<<1040, 256>>>();
    k_fft_x_gmul<<<1040, 256>>>(cell);
    k_fft_y<1><<<1040, 256>>>();
    k_fft_z_inv<<<1024, 256>>>();

    k_gather<<<ab, 256>>>(cell, out, n);
}

// round 8
// speedup vs baseline: 1.1616x; 1.1616x over previous
#include <cuda_runtime.h>
#include <math.h>

#define N3 (128*128*128)
#define NZH 65                       // Hermitian half length along z
#define KLINES (128*65)              // 8320 k-space lines for y/x passes

__device__ float2 d_kmesh[128*128*NZH];  // half-spectrum mesh (8.5 MB)
__device__ float  d_rho[N3];             // dense real mesh (8 MB)

// ---------------------------------------------------------------------------
__device__ __forceinline__ float2 cadd(float2 a, float2 b){ return make_float2(a.x+b.x, a.y+b.y); }
__device__ __forceinline__ float2 csub(float2 a, float2 b){ return make_float2(a.x-b.x, a.y-b.y); }
__device__ __forceinline__ float2 cmul(float2 a, float2 w){ return make_float2(a.x*w.x-a.y*w.y, a.x*w.y+a.y*w.x); }

__device__ __forceinline__ void inv3x3(const float* __restrict__ cell,
                                       float inv[9], float& det) {
    float a = __ldg(cell+0), b = __ldg(cell+1), c = __ldg(cell+2);
    float d = __ldg(cell+3), e = __ldg(cell+4), f = __ldg(cell+5);
    float g = __ldg(cell+6), h = __ldg(cell+7), i = __ldg(cell+8);
    float C00 =  (e*i - f*h), C01 = -(d*i - f*g), C02 =  (d*h - e*g);
    float C10 = -(b*i - c*h), C11 =  (a*i - c*g), C12 = -(a*h - b*g);
    float C20 =  (b*f - c*e), C21 = -(a*f - c*d), C22 =  (a*e - b*d);
    det = a*C00 + b*C01 + c*C02;
    float idet = 1.0f / det;
    inv[0]=C00*idet; inv[1]=C10*idet; inv[2]=C20*idet;
    inv[3]=C01*idet; inv[4]=C11*idet; inv[5]=C21*idet;
    inv[6]=C02*idet; inv[7]=C12*idet; inv[8]=C22*idet;
}

__global__ void k_zero() {
    int i = blockIdx.x * blockDim.x + threadIdx.x;   // 524288 float4s (8 MB)
    ((float4*)d_rho)[i] = make_float4(0.f, 0.f, 0.f, 0.f);
}

// ---------------------------------------------------------------------------
// Radix-4 Stockham stage — PER-WARP: warp w owns line w (segment w*129).
// lane = butterfly index t. All shared traffic intra-warp.
// ---------------------------------------------------------------------------
template<int CONJ, int S>
__device__ __forceinline__ void r4_stage(const float2* __restrict__ cur,
                                         float2* __restrict__ nxt,
                                         const float2* __restrict__ tw,
                                         int off, int t) {
    int q  = t & (S - 1);
    int sp = t - q;
    float2 a0 = cur[off + t];
    float2 a1 = cur[off + t + 32];
    float2 a2 = cur[off + t + 64];
    float2 a3 = cur[off + t + 96];
    float2 t02 = cadd(a0, a2), d02 = csub(a0, a2);
    float2 t13 = cadd(a1, a3), d13 = csub(a1, a3);
    float2 y0 = cadd(t02, t13);
    float2 y2 = csub(t02, t13);
    float2 jd;
    if (CONJ) jd = make_float2(-d13.y,  d13.x);
    else      jd = make_float2( d13.y, -d13.x);
    float2 y1 = cadd(d02, jd);
    float2 y3 = csub(d02, jd);
    float2 w1 = tw[sp], w2 = tw[2*sp], w3 = tw[3*sp];
    if (CONJ) { w1.y = -w1.y; w2.y = -w2.y; w3.y = -w3.y; }
    int o = off + t + 3*sp;
    nxt[o]       = y0;
    nxt[o + S]   = cmul(y1, w1);
    nxt[o + 2*S] = cmul(y2, w2);
    nxt[o + 3*S] = cmul(y3, w3);
}

// three radix-4 stages, warp-synchronous only; result (pre final r2) in B
template<int CONJ>
__device__ __forceinline__ void fft_r4_stages(float2* A, float2* B,
                                              const float2* tw,
                                              int off, int lane) {
    r4_stage<CONJ, 1 >(A, B, tw, off, lane); __syncwarp();
    r4_stage<CONJ, 4 >(B, A, tw, off, lane); __syncwarp();
    r4_stage<CONJ, 16>(A, B, tw, off, lane); __syncwarp();
}

// per-warp twiddle-free final radix-2 (src -> dst, natural order)
__device__ __forceinline__ void r2_final_warp(const float2* __restrict__ src,
                                              float2* __restrict__ dst,
                                              int off, int lane) {
    #pragma unroll
    for (int t = lane; t < 64; t += 32) {
        float2 a = src[off + t], b = src[off + t + 64];
        dst[off + t]      = cadd(a, b);
        dst[off + t + 64] = csub(a, b);
    }
}

__device__ __forceinline__ void init_tw(float2* tw, int tid) {
    if (tid < 128) {
        float s, c;
        sincospif((float)tid * (1.0f / 64.0f), &s, &c);
        tw[tid] = make_float2(c, -s);
    }
}

// ---------------------------------------------------------------------------
// z forward r2c (two-for-one): warp w handles real lines 2*gw, 2*gw+1.
// 1024 blocks x 8 warps. One block barrier (twiddle table).
// ---------------------------------------------------------------------------
__global__ void k_fft_z_fwd() {
    __shared__ float2 bufA[8 * 129];
    __shared__ float2 bufB[8 * 129];
    __shared__ float2 tw[128];
    int tid = threadIdx.x, lane = tid & 31, w = tid >> 5;
    int off = w * 129;
    int gw = blockIdx.x * 8 + w;
    init_tw(tw, tid);
    const float* rpA = d_rho + (2*gw) * 128;
    const float* rpB = rpA + 128;
    #pragma unroll
    for (int l = lane; l < 128; l += 32)
        bufA[off + l] = make_float2(rpA[l], rpB[l]);
    __syncthreads();                          // tw visibility (covers loads too)
    fft_r4_stages<0>(bufA, bufB, tw, off, lane);
    r2_final_warp(bufB, bufA, off, lane);
    __syncwarp();
    // Hermitian unpack for the two packed real lines
    float2* oA = d_kmesh + (2*gw) * NZH;
    float2* oB = oA + NZH;
    for (int k = lane; k < 65; k += 32) {
        float2 Ck = bufA[off + k];
        float2 Cm = bufA[off + ((128 - k) & 127)];
        oA[k] = make_float2(0.5f*(Ck.x + Cm.x),  0.5f*(Ck.y - Cm.y));
        oB[k] = make_float2(0.5f*(Ck.y + Cm.y), -0.5f*(Ck.x - Cm.x));
    }
}

// ---------------------------------------------------------------------------
// z inverse c2r (two-for-one): warp w handles half-spectrum lines 2*gw, 2*gw+1.
// ---------------------------------------------------------------------------
__global__ void k_fft_z_inv() {
    __shared__ float2 bufA[8 * 129];
    __shared__ float2 bufB[8 * 129];
    __shared__ float2 tw[128];
    int tid = threadIdx.x, lane = tid & 31, w = tid >> 5;
    int off = w * 129;
    int gw = blockIdx.x * 8 + w;
    init_tw(tw, tid);
    const float2* iA = d_kmesh + (2*gw) * NZH;
    const float2* iB = iA + NZH;
    for (int k = lane; k < 65; k += 32) {
        float2 A = iA[k], B = iB[k];
        bufA[off + k] = make_float2(A.x - B.y, A.y + B.x);
        if (k >= 1 && k <= 63)
            bufA[off + 128 - k] = make_float2(A.x + B.y, B.x - A.y);
    }
    __syncthreads();                          // tw visibility
    fft_r4_stages<1>(bufA, bufB, tw, off, lane);
    float* rpA = d_rho + (2*gw) * 128;
    float* rpB = rpA + 128;
    #pragma unroll
    for (int l = lane; l < 64; l += 32) {
        float2 a = bufB[off + l], b = bufB[off + l + 64];
        float2 su = cadd(a, b), df = csub(a, b);
        rpA[l]      = su.x;
        rpB[l]      = su.y;
        rpA[l + 64] = df.x;
        rpB[l + 64] = df.y;
    }
}

// ---------------------------------------------------------------------------
// y pass: warp w handles line L = blockIdx*8 + w (elements at x*8320 + y*65 + kz).
// 1040 blocks. One block barrier.
// ---------------------------------------------------------------------------
template<int CONJ>
__global__ void k_fft_y() {
    __shared__ float2 bufA[8 * 129];
    __shared__ float2 bufB[8 * 129];
    __shared__ float2 tw[128];
    int tid = threadIdx.x, lane = tid & 31, w = tid >> 5;
    int off = w * 129;
    init_tw(tw, tid);
    int L = blockIdx.x * 8 + w;
    int x = L / NZH, kz = L - x * NZH;
    float2* base = d_kmesh + x * (128 * NZH) + kz;
    #pragma unroll
    for (int l = lane; l < 128; l += 32)
        bufA[off + l] = base[l * NZH];
    __syncthreads();                          // tw visibility
    fft_r4_stages<CONJ>(bufA, bufB, tw, off, lane);
    #pragma unroll
    for (int l = lane; l < 64; l += 32) {
        float2 a = bufB[off + l], b = bufB[off + l + 64];
        base[l * NZH]        = cadd(a, b);
        base[(l + 64) * NZH] = csub(a, b);
    }
}

// ---------------------------------------------------------------------------
// Fused x pass: fwd FFT along x, G(k)/V multiply, inv FFT along x. 1040 blocks.
// Striped (coalesced) global IO -> two block barriers; stages warp-local.
// ---------------------------------------------------------------------------
__global__ void k_fft_x_gmul(const float* __restrict__ cell) {
    __shared__ float2 bufA[8 * 129];
    __shared__ float2 bufB[8 * 129];
    __shared__ float2 tw[128];
    int tid = threadIdx.x, lane = tid & 31, w = tid >> 5;
    int off = w * 129;
    int L0 = blockIdx.x * 8;
    init_tw(tw, tid);
    float inv[9]; float det;
    inv3x3(cell, inv, det);
    const float TWO_PI = 6.283185307179586f;
    float b0x = TWO_PI*inv[0], b0y = TWO_PI*inv[3], b0z = TWO_PI*inv[6];
    float b1x = TWO_PI*inv[1], b1y = TWO_PI*inv[4], b1z = TWO_PI*inv[7];
    float b2x = TWO_PI*inv[2], b2y = TWO_PI*inv[5], b2z = TWO_PI*inv[8];
    float ivol = 1.0f / fabsf(det);
    int L = L0 + w;
    int yy = L / NZH, kz = L - yy * NZH;
    float mj = (float)(yy - ((yy >= 64) ? 128 : 0));
    float mk = (float)kz;
    // striped coalesced load
    #pragma unroll
    for (int e = tid; e < 1024; e += 256) {
        int c = e & 7, l = e >> 3;
        bufA[c * 129 + l] = d_kmesh[L0 + c + l * KLINES];
    }
    __syncthreads();
    fft_r4_stages<0>(bufA, bufB, tw, off, lane);
    r2_final_warp(bufB, bufA, off, lane);
    __syncwarp();
    // G(k)/V on own line in natural order
    #pragma unroll
    for (int xk = lane; xk < 128; xk += 32) {
        float mi = (float)(xk - ((xk >= 64) ? 128 : 0));
        float kx = mi * b0x + mj * b1x + mk * b2x;
        float ky = mi * b0y + mj * b1y + mk * b2y;
        float kzv = mi * b0z + mj * b1z + mk * b2z;
        float ksq = kx*kx + ky*ky + kzv*kzv;
        float g = 0.0f;
        if (ksq != 0.0f)
            g = 12.566370614359172f / ksq * expf(-0.5f * ksq) * ivol;
        float2 v = bufA[off + xk];
        v.x *= g; v.y *= g;
        bufA[off + xk] = v;
    }
    __syncwarp();
    fft_r4_stages<1>(bufA, bufB, tw, off, lane);
    __syncthreads();
    // striped coalesced store with fused final radix-2
    #pragma unroll
    for (int e = tid; e < 512; e += 256) {
        int c = e & 7, l = e >> 3;
        float2 a = bufB[c * 129 + l], b = bufB[c * 129 + l + 64];
        d_kmesh[L0 + c + l * KLINES]        = cadd(a, b);
        d_kmesh[L0 + c + (l + 64) * KLINES] = csub(a, b);
    }
}

// ---------------------------------------------------------------------------
// spline weights + stencil
// ---------------------------------------------------------------------------
__device__ __forceinline__ void spline_w4(float x, float* w) {
    float x2 = x * x, x3 = x2 * x;
    const float s = 1.0f / 48.0f;
    w[0] = ( 1.0f -  6.0f*x + 12.0f*x2 -  8.0f*x3) * s;
    w[1] = (23.0f - 30.0f*x - 12.0f*x2 + 24.0f*x3) * s;
    w[2] = (23.0f + 30.0f*x - 12.0f*x2 - 24.0f*x3) * s;
    w[3] = ( 1.0f +  6.0f*x + 12.0f*x2 +  8.0f*x3) * s;
}

__device__ __forceinline__ int atom_stencil(
    const float* __restrict__ cell, const float* __restrict__ pos, int a,
    float* wx, float* wy, float* wz, int* ix, int* iy)
{
    float inv[9]; float det;
    inv3x3(cell, inv, det);
    float p0 = pos[3*a], p1 = pos[3*a+1], p2 = pos[3*a+2];
    float r0 = (p0*inv[0] + p1*inv[3] + p2*inv[6]) * 128.0f;
    float r1 = (p0*inv[1] + p1*inv[4] + p2*inv[7]) * 128.0f;
    float r2 = (p0*inv[2] + p1*inv[5] + p2*inv[8]) * 128.0f;
    int i0 = __float2int_rd(r0);
    int i1 = __float2int_rd(r1);
    int i2 = __float2int_rd(r2);
    spline_w4(r0 - (float)i0 - 0.5f, wx);
    spline_w4(r1 - (float)i1 - 0.5f, wy);
    spline_w4(r2 - (float)i2 - 0.5f, wz);
    #pragma unroll
    for (int s = 0; s < 4; s++) {
        ix[s] = (i0 + s - 1 + 128) & 127;
        iy[s] = (i1 + s - 1 + 128) & 127;
    }
    return i2;
}

__device__ __forceinline__ void pad_quads(const float* wz, int off,
                                          float* q0, float* q1) {
    switch (off) {
    case 0: q0[0]=wz[0]; q0[1]=wz[1]; q0[2]=wz[2]; q0[3]=wz[3]; break;
    case 1: q0[1]=wz[0]; q0[2]=wz[1]; q0[3]=wz[2]; q1[0]=wz[3]; break;
    case 2: q0[2]=wz[0]; q0[3]=wz[1]; q1[0]=wz[2]; q1[1]=wz[3]; break;
    default:q0[3]=wz[0]; q1[0]=wz[1]; q1[1]=wz[2]; q1[2]=wz[3]; break;
    }
}

__device__ __forceinline__ void red4(float* p, float a, float b, float c, float d) {
    asm volatile("red.global.add.v4.f32 [%0], {%1, %2, %3, %4};"
                 :: "l"(p), "f"(a), "f"(b), "f"(c), "f"(d) : "memory");
}
__device__ __forceinline__ void red2(float* p, float a, float b) {
    asm volatile("red.global.add.v2.f32 [%0], {%1, %2};"
                 :: "l"(p), "f"(a), "f"(b) : "memory");
}
__device__ __forceinline__ void red1(float* p, float a) {
    asm volatile("red.global.add.f32 [%0], %1;"
                 :: "l"(p), "f"(a) : "memory");
}

// ---------------------------------------------------------------------------
__global__ void k_scatter(const float* __restrict__ cell,
                          const float* __restrict__ pos,
                          const float* __restrict__ chg, int n) {
    int a = blockIdx.x * blockDim.x + threadIdx.x;
    if (a >= n) return;
    float wx[4], wy[4], wz[4];
    int ix[4], iy[4];
    int i2 = atom_stencil(cell, pos, a, wx, wy, wz, ix, iy);
    float c = chg[a];
    int zlo = i2 - 1;
    if (zlo >= 0 && zlo <= 124) {
        int Q0 = zlo & ~3, off = zlo & 3;
        #pragma unroll
        for (int i = 0; i < 4; i++) {
            float cwi = c * wx[i];
            int ox = ix[i] << 14;
            #pragma unroll
            for (int j = 0; j < 4; j++) {
                float s = cwi * wy[j];
                float* p = &d_rho[ox + (iy[j] << 7) + Q0];
                switch (off) {
                case 0:
                    red4(p, s*wz[0], s*wz[1], s*wz[2], s*wz[3]);
                    break;
                case 1:
                    red4(p, 0.0f, s*wz[0], s*wz[1], s*wz[2]);
                    red1(p + 4, s*wz[3]);
                    break;
                case 2:
                    red2(p + 2, s*wz[0], s*wz[1]);
                    red2(p + 4, s*wz[2], s*wz[3]);
                    break;
                default:
                    red1(p + 3, s*wz[0]);
                    red4(p + 4, s*wz[1], s*wz[2], s*wz[3], 0.0f);
                    break;
                }
            }
        }
    } else {
        int iz[4];
        #pragma unroll
        for (int s = 0; s < 4; s++) iz[s] = (zlo + s + 128) & 127;
        #pragma unroll
        for (int i = 0; i < 4; i++) {
            float cwi = c * wx[i];
            int ox = ix[i] << 14;
            #pragma unroll
            for (int j = 0; j < 4; j++) {
                float cwij = cwi * wy[j];
                int oxy = ox + (iy[j] << 7);
                #pragma unroll
                for (int k = 0; k < 4; k++)
                    red1(&d_rho[oxy + iz[k]], cwij * wz[k]);
            }
        }
    }
}

// ---------------------------------------------------------------------------
__global__ void k_gather(const float* __restrict__ cell,
                         const float* __restrict__ pos,
                         const float* __restrict__ chg,
                         float* __restrict__ out, int n) {
    int a = blockIdx.x * blockDim.x + threadIdx.x;
    if (a >= n) return;
    float wx[4], wy[4], wz[4];
    int ix[4], iy[4];
    int i2 = atom_stencil(cell, pos, a, wx, wy, wz, ix, iy);
    float sum = 0.0f;
    int zlo = i2 - 1;
    if (zlo >= 0 && zlo <= 124) {
        int Q0 = zlo & ~3, off = zlo & 3;
        float q0[4] = {0,0,0,0}, q1[4] = {0,0,0,0};
        pad_quads(wz, off, q0, q1);
        #pragma unroll
        for (int i = 0; i < 4; i++) {
            float wi = wx[i];
            int ox = ix[i] << 14;
            #pragma unroll
            for (int j = 0; j < 4; j++) {
                const float* p = &d_rho[ox + (iy[j] << 7) + Q0];
                float4 v0 = __ldg((const float4*)p);
                float acc = v0.x*q0[0] + v0.y*q0[1] + v0.z*q0[2] + v0.w*q0[3];
                if (off) {
                    float4 v1 = __ldg((const float4*)(p + 4));
                    acc += v1.x*q1[0] + v1.y*q1[1] + v1.z*q1[2] + v1.w*q1[3];
                }
                sum += wi * wy[j] * acc;
            }
        }
    } else {
        int iz[4];
        #pragma unroll
        for (int s = 0; s < 4; s++) iz[s] = (zlo + s + 128) & 127;
        #pragma unroll
        for (int i = 0; i < 4; i++) {
            float wi = wx[i];
            int ox = ix[i] << 14;
            #pragma unroll
            for (int j = 0; j < 4; j++) {
                int oxy = ox + (iy[j] << 7);
                float acc = 0.0f;
                #pragma unroll
                for (int k = 0; k < 4; k++)
                    acc += wz[k] * d_rho[oxy + iz[k]];
                sum += wi * wy[j] * acc;
            }
        }
    }
    out[a] = sum - chg[a] * 0.7978845608028654f;
}

// ---------------------------------------------------------------------------
extern "C" void kernel_launch(void* const* d_in, const int* in_sizes, int n_in,
                              void* d_out, int out_size) {
    const float* cell = (const float*)d_in[0];
    const float* pos  = (const float*)d_in[1];
    const float* chg  = (const float*)d_in[2];
    float* out = (float*)d_out;
    int n = in_sizes[2];

    k_zero<<<2048, 256>>>();

    int ab = (n + 255) / 256;
    k_scatter<<<ab, 256>>>(cell, pos, chg, n);

    k_fft_z_fwd<<<1024, 256>>>();
    k_fft_y<0><<<1040, 256>>>();
    k_fft_x_gmul<<<1040, 256>>>(cell);
    k_fft_y<1><<<1040, 256>>>();
    k_fft_z_inv<<<1024, 256>>>();

    k_gather<<<ab, 256>>>(cell, pos, chg, out, n);
}

// round 9
// speedup vs baseline: 1.2215x; 1.0515x over previous
#include <cuda_runtime.h>
#include <math.h>

#define N3 (128*128*128)
#define NZH 65                       // Hermitian half length along z
#define KLINES (128*65)              // 8320 k-space lines for y/x passes

__device__ float2 d_kmesh[128*128*NZH];  // half-spectrum mesh (8.5 MB)
__device__ float  d_rho[N3];             // dense real mesh (8 MB)

// ---------------------------------------------------------------------------
__device__ __forceinline__ float2 cadd(float2 a, float2 b){ return make_float2(a.x+b.x, a.y+b.y); }
__device__ __forceinline__ float2 csub(float2 a, float2 b){ return make_float2(a.x-b.x, a.y-b.y); }
__device__ __forceinline__ float2 cmul(float2 a, float2 w){ return make_float2(a.x*w.x-a.y*w.y, a.x*w.y+a.y*w.x); }

__device__ __forceinline__ void inv3x3(const float* __restrict__ cell,
                                       float inv[9], float& det) {
    float a = __ldg(cell+0), b = __ldg(cell+1), c = __ldg(cell+2);
    float d = __ldg(cell+3), e = __ldg(cell+4), f = __ldg(cell+5);
    float g = __ldg(cell+6), h = __ldg(cell+7), i = __ldg(cell+8);
    float C00 =  (e*i - f*h), C01 = -(d*i - f*g), C02 =  (d*h - e*g);
    float C10 = -(b*i - c*h), C11 =  (a*i - c*g), C12 = -(a*h - b*g);
    float C20 =  (b*f - c*e), C21 = -(a*f - c*d), C22 =  (a*e - b*d);
    det = a*C00 + b*C01 + c*C02;
    float idet = 1.0f / det;
    inv[0]=C00*idet; inv[1]=C10*idet; inv[2]=C20*idet;
    inv[3]=C01*idet; inv[4]=C11*idet; inv[5]=C21*idet;
    inv[6]=C02*idet; inv[7]=C12*idet; inv[8]=C22*idet;
}

__global__ void k_zero() {
    int i = blockIdx.x * blockDim.x + threadIdx.x;   // 524288 float4s (8 MB)
    ((float4*)d_rho)[i] = make_float4(0.f, 0.f, 0.f, 0.f);
}

// ---------------------------------------------------------------------------
// Radix-4 Stockham stage — PER-WARP: warp w owns line w (segment w*129).
// lane = butterfly index t. All shared traffic intra-warp.
// ---------------------------------------------------------------------------
template<int CONJ, int S>
__device__ __forceinline__ void r4_stage(const float2* __restrict__ cur,
                                         float2* __restrict__ nxt,
                                         const float2* __restrict__ tw,
                                         int off, int t) {
    int q  = t & (S - 1);
    int sp = t - q;
    float2 a0 = cur[off + t];
    float2 a1 = cur[off + t + 32];
    float2 a2 = cur[off + t + 64];
    float2 a3 = cur[off + t + 96];
    float2 t02 = cadd(a0, a2), d02 = csub(a0, a2);
    float2 t13 = cadd(a1, a3), d13 = csub(a1, a3);
    float2 y0 = cadd(t02, t13);
    float2 y2 = csub(t02, t13);
    float2 jd;
    if (CONJ) jd = make_float2(-d13.y,  d13.x);
    else      jd = make_float2( d13.y, -d13.x);
    float2 y1 = cadd(d02, jd);
    float2 y3 = csub(d02, jd);
    float2 w1 = tw[sp], w2 = tw[2*sp], w3 = tw[3*sp];
    if (CONJ) { w1.y = -w1.y; w2.y = -w2.y; w3.y = -w3.y; }
    int o = off + t + 3*sp;
    nxt[o]       = y0;
    nxt[o + S]   = cmul(y1, w1);
    nxt[o + 2*S] = cmul(y2, w2);
    nxt[o + 3*S] = cmul(y3, w3);
}

// three radix-4 stages, warp-synchronous only; result (pre final r2) in B
template<int CONJ>
__device__ __forceinline__ void fft_r4_stages(float2* A, float2* B,
                                              const float2* tw,
                                              int off, int lane) {
    r4_stage<CONJ, 1 >(A, B, tw, off, lane); __syncwarp();
    r4_stage<CONJ, 4 >(B, A, tw, off, lane); __syncwarp();
    r4_stage<CONJ, 16>(A, B, tw, off, lane); __syncwarp();
}

// per-warp twiddle-free final radix-2 (src -> dst, natural order)
__device__ __forceinline__ void r2_final_warp(const float2* __restrict__ src,
                                              float2* __restrict__ dst,
                                              int off, int lane) {
    #pragma unroll
    for (int t = lane; t < 64; t += 32) {
        float2 a = src[off + t], b = src[off + t + 64];
        dst[off + t]      = cadd(a, b);
        dst[off + t + 64] = csub(a, b);
    }
}

__device__ __forceinline__ void init_tw(float2* tw, int tid) {
    if (tid < 128) {
        float s, c;
        sincospif((float)tid * (1.0f / 64.0f), &s, &c);
        tw[tid] = make_float2(c, -s);
    }
}

// ---------------------------------------------------------------------------
// z forward r2c (two-for-one): warp w handles real lines 2*gw, 2*gw+1.
// 1024 blocks x 8 warps. One block barrier (twiddle table).
// ---------------------------------------------------------------------------
__global__ void k_fft_z_fwd() {
    __shared__ float2 bufA[8 * 129];
    __shared__ float2 bufB[8 * 129];
    __shared__ float2 tw[128];
    int tid = threadIdx.x, lane = tid & 31, w = tid >> 5;
    int off = w * 129;
    int gw = blockIdx.x * 8 + w;
    init_tw(tw, tid);
    const float* rpA = d_rho + (2*gw) * 128;
    const float* rpB = rpA + 128;
    #pragma unroll
    for (int l = lane; l < 128; l += 32)
        bufA[off + l] = make_float2(rpA[l], rpB[l]);
    __syncthreads();                          // tw visibility (covers loads too)
    fft_r4_stages<0>(bufA, bufB, tw, off, lane);
    r2_final_warp(bufB, bufA, off, lane);
    __syncwarp();
    // Hermitian unpack for the two packed real lines
    float2* oA = d_kmesh + (2*gw) * NZH;
    float2* oB = oA + NZH;
    for (int k = lane; k < 65; k += 32) {
        float2 Ck = bufA[off + k];
        float2 Cm = bufA[off + ((128 - k) & 127)];
        oA[k] = make_float2(0.5f*(Ck.x + Cm.x),  0.5f*(Ck.y - Cm.y));
        oB[k] = make_float2(0.5f*(Ck.y + Cm.y), -0.5f*(Ck.x - Cm.x));
    }
}

// ---------------------------------------------------------------------------
// z inverse c2r (two-for-one): warp w handles half-spectrum lines 2*gw, 2*gw+1.
// ---------------------------------------------------------------------------
__global__ void k_fft_z_inv() {
    __shared__ float2 bufA[8 * 129];
    __shared__ float2 bufB[8 * 129];
    __shared__ float2 tw[128];
    int tid = threadIdx.x, lane = tid & 31, w = tid >> 5;
    int off = w * 129;
    int gw = blockIdx.x * 8 + w;
    init_tw(tw, tid);
    const float2* iA = d_kmesh + (2*gw) * NZH;
    const float2* iB = iA + NZH;
    for (int k = lane; k < 65; k += 32) {
        float2 A = iA[k], B = iB[k];
        bufA[off + k] = make_float2(A.x - B.y, A.y + B.x);
        if (k >= 1 && k <= 63)
            bufA[off + 128 - k] = make_float2(A.x + B.y, B.x - A.y);
    }
    __syncthreads();                          // tw visibility
    fft_r4_stages<1>(bufA, bufB, tw, off, lane);
    float* rpA = d_rho + (2*gw) * 128;
    float* rpB = rpA + 128;
    #pragma unroll
    for (int l = lane; l < 64; l += 32) {
        float2 a = bufB[off + l], b = bufB[off + l + 64];
        float2 su = cadd(a, b), df = csub(a, b);
        rpA[l]      = su.x;
        rpB[l]      = su.y;
        rpA[l + 64] = df.x;
        rpB[l + 64] = df.y;
    }
}

// ---------------------------------------------------------------------------
// y pass, HYBRID: striped coalesced block IO + warp-local stages.
// lines (x, kz) = L = blockIdx*8 + c, elements at x*8320 + y*65 + kz. 1040 blocks.
// ---------------------------------------------------------------------------
template<int CONJ>
__global__ void k_fft_y() {
    __shared__ float2 bufA[8 * 129];
    __shared__ float2 bufB[8 * 129];
    __shared__ float2 tw[128];
    __shared__ int lineBase[8];
    int tid = threadIdx.x, lane = tid & 31, w = tid >> 5;
    int off = w * 129;
    init_tw(tw, tid);
    if (tid < 8) {
        int L = blockIdx.x * 8 + tid;
        int x = L / NZH, kz = L - x * NZH;
        lineBase[tid] = x * (128 * NZH) + kz;
    }
    __syncthreads();
    // striped coalesced load: consecutive threads hit consecutive lines
    #pragma unroll
    for (int e = tid; e < 1024; e += 256) {
        int c = e & 7, l = e >> 3;
        bufA[c * 129 + l] = d_kmesh[lineBase[c] + l * NZH];
    }
    __syncthreads();
    fft_r4_stages<CONJ>(bufA, bufB, tw, off, lane);
    __syncthreads();
    // striped coalesced store with fused final radix-2
    #pragma unroll
    for (int e = tid; e < 512; e += 256) {
        int c = e & 7, l = e >> 3;
        float2 a = bufB[c * 129 + l], b = bufB[c * 129 + l + 64];
        d_kmesh[lineBase[c] + l * NZH]        = cadd(a, b);
        d_kmesh[lineBase[c] + (l + 64) * NZH] = csub(a, b);
    }
}

// ---------------------------------------------------------------------------
// Fused x pass: fwd FFT along x, G(k)/V multiply, inv FFT along x. 1040 blocks.
// Striped (coalesced) global IO -> two block barriers; stages warp-local.
// ---------------------------------------------------------------------------
__global__ void k_fft_x_gmul(const float* __restrict__ cell) {
    __shared__ float2 bufA[8 * 129];
    __shared__ float2 bufB[8 * 129];
    __shared__ float2 tw[128];
    int tid = threadIdx.x, lane = tid & 31, w = tid >> 5;
    int off = w * 129;
    int L0 = blockIdx.x * 8;
    init_tw(tw, tid);
    float inv[9]; float det;
    inv3x3(cell, inv, det);
    const float TWO_PI = 6.283185307179586f;
    float b0x = TWO_PI*inv[0], b0y = TWO_PI*inv[3], b0z = TWO_PI*inv[6];
    float b1x = TWO_PI*inv[1], b1y = TWO_PI*inv[4], b1z = TWO_PI*inv[7];
    float b2x = TWO_PI*inv[2], b2y = TWO_PI*inv[5], b2z = TWO_PI*inv[8];
    float ivol = 1.0f / fabsf(det);
    int L = L0 + w;
    int yy = L / NZH, kz = L - yy * NZH;
    float mj = (float)(yy - ((yy >= 64) ? 128 : 0));
    float mk = (float)kz;
    // striped coalesced load
    #pragma unroll
    for (int e = tid; e < 1024; e += 256) {
        int c = e & 7, l = e >> 3;
        bufA[c * 129 + l] = d_kmesh[L0 + c + l * KLINES];
    }
    __syncthreads();
    fft_r4_stages<0>(bufA, bufB, tw, off, lane);
    r2_final_warp(bufB, bufA, off, lane);
    __syncwarp();
    // G(k)/V on own line in natural order
    #pragma unroll
    for (int xk = lane; xk < 128; xk += 32) {
        float mi = (float)(xk - ((xk >= 64) ? 128 : 0));
        float kx = mi * b0x + mj * b1x + mk * b2x;
        float ky = mi * b0y + mj * b1y + mk * b2y;
        float kzv = mi * b0z + mj * b1z + mk * b2z;
        float ksq = kx*kx + ky*ky + kzv*kzv;
        float g = 0.0f;
        if (ksq != 0.0f)
            g = 12.566370614359172f / ksq * expf(-0.5f * ksq) * ivol;
        float2 v = bufA[off + xk];
        v.x *= g; v.y *= g;
        bufA[off + xk] = v;
    }
    __syncwarp();
    fft_r4_stages<1>(bufA, bufB, tw, off, lane);
    __syncthreads();
    // striped coalesced store with fused final radix-2
    #pragma unroll
    for (int e = tid; e < 512; e += 256) {
        int c = e & 7, l = e >> 3;
        float2 a = bufB[c * 129 + l], b = bufB[c * 129 + l + 64];
        d_kmesh[L0 + c + l * KLINES]        = cadd(a, b);
        d_kmesh[L0 + c + (l + 64) * KLINES] = csub(a, b);
    }
}

// ---------------------------------------------------------------------------
// spline weights + stencil
// ---------------------------------------------------------------------------
__device__ __forceinline__ void spline_w4(float x, float* w) {
    float x2 = x * x, x3 = x2 * x;
    const float s = 1.0f / 48.0f;
    w[0] = ( 1.0f -  6.0f*x + 12.0f*x2 -  8.0f*x3) * s;
    w[1] = (23.0f - 30.0f*x - 12.0f*x2 + 24.0f*x3) * s;
    w[2] = (23.0f + 30.0f*x - 12.0f*x2 - 24.0f*x3) * s;
    w[3] = ( 1.0f +  6.0f*x + 12.0f*x2 +  8.0f*x3) * s;
}

__device__ __forceinline__ int atom_stencil(
    const float* __restrict__ cell, const float* __restrict__ pos, int a,
    float* wx, float* wy, float* wz, int* ix, int* iy)
{
    float inv[9]; float det;
    inv3x3(cell, inv, det);
    float p0 = pos[3*a], p1 = pos[3*a+1], p2 = pos[3*a+2];
    float r0 = (p0*inv[0] + p1*inv[3] + p2*inv[6]) * 128.0f;
    float r1 = (p0*inv[1] + p1*inv[4] + p2*inv[7]) * 128.0f;
    float r2 = (p0*inv[2] + p1*inv[5] + p2*inv[8]) * 128.0f;
    int i0 = __float2int_rd(r0);
    int i1 = __float2int_rd(r1);
    int i2 = __float2int_rd(r2);
    spline_w4(r0 - (float)i0 - 0.5f, wx);
    spline_w4(r1 - (float)i1 - 0.5f, wy);
    spline_w4(r2 - (float)i2 - 0.5f, wz);
    #pragma unroll
    for (int s = 0; s < 4; s++) {
        ix[s] = (i0 + s - 1 + 128) & 127;
        iy[s] = (i1 + s - 1 + 128) & 127;
    }
    return i2;
}

__device__ __forceinline__ void pad_quads(const float* wz, int off,
                                          float* q0, float* q1) {
    switch (off) {
    case 0: q0[0]=wz[0]; q0[1]=wz[1]; q0[2]=wz[2]; q0[3]=wz[3]; break;
    case 1: q0[1]=wz[0]; q0[2]=wz[1]; q0[3]=wz[2]; q1[0]=wz[3]; break;
    case 2: q0[2]=wz[0]; q0[3]=wz[1]; q1[0]=wz[2]; q1[1]=wz[3]; break;
    default:q0[3]=wz[0]; q1[0]=wz[1]; q1[1]=wz[2]; q1[2]=wz[3]; break;
    }
}

__device__ __forceinline__ void red4(float* p, float a, float b, float c, float d) {
    asm volatile("red.global.add.v4.f32 [%0], {%1, %2, %3, %4};"
                 :: "l"(p), "f"(a), "f"(b), "f"(c), "f"(d) : "memory");
}
__device__ __forceinline__ void red2(float* p, float a, float b) {
    asm volatile("red.global.add.v2.f32 [%0], {%1, %2};"
                 :: "l"(p), "f"(a), "f"(b) : "memory");
}
__device__ __forceinline__ void red1(float* p, float a) {
    asm volatile("red.global.add.f32 [%0], %1;"
                 :: "l"(p), "f"(a) : "memory");
}

// ---------------------------------------------------------------------------
__global__ void k_scatter(const float* __restrict__ cell,
                          const float* __restrict__ pos,
                          const float* __restrict__ chg, int n) {
    int a = blockIdx.x * blockDim.x + threadIdx.x;
    if (a >= n) return;
    float wx[4], wy[4], wz[4];
    int ix[4], iy[4];
    int i2 = atom_stencil(cell, pos, a, wx, wy, wz, ix, iy);
    float c = chg[a];
    int zlo = i2 - 1;
    if (zlo >= 0 && zlo <= 124) {
        int Q0 = zlo & ~3, off = zlo & 3;
        #pragma unroll
        for (int i = 0; i < 4; i++) {
            float cwi = c * wx[i];
            int ox = ix[i] << 14;
            #pragma unroll
            for (int j = 0; j < 4; j++) {
                float s = cwi * wy[j];
                float* p = &d_rho[ox + (iy[j] << 7) + Q0];
                switch (off) {
                case 0:
                    red4(p, s*wz[0], s*wz[1], s*wz[2], s*wz[3]);
                    break;
                case 1:
                    red4(p, 0.0f, s*wz[0], s*wz[1], s*wz[2]);
                    red1(p + 4, s*wz[3]);
                    break;
                case 2:
                    red2(p + 2, s*wz[0], s*wz[1]);
                    red2(p + 4, s*wz[2], s*wz[3]);
                    break;
                default:
                    red1(p + 3, s*wz[0]);
                    red4(p + 4, s*wz[1], s*wz[2], s*wz[3], 0.0f);
                    break;
                }
            }
        }
    } else {
        int iz[4];
        #pragma unroll
        for (int s = 0; s < 4; s++) iz[s] = (zlo + s + 128) & 127;
        #pragma unroll
        for (int i = 0; i < 4; i++) {
            float cwi = c * wx[i];
            int ox = ix[i] << 14;
            #pragma unroll
            for (int j = 0; j < 4; j++) {
                float cwij = cwi * wy[j];
                int oxy = ox + (iy[j] << 7);
                #pragma unroll
                for (int k = 0; k < 4; k++)
                    red1(&d_rho[oxy + iz[k]], cwij * wz[k]);
            }
        }
    }
}

// ---------------------------------------------------------------------------
__global__ void k_gather(const float* __restrict__ cell,
                         const float* __restrict__ pos,
                         const float* __restrict__ chg,
                         float* __restrict__ out, int n) {
    int a = blockIdx.x * blockDim.x + threadIdx.x;
    if (a >= n) return;
    float wx[4], wy[4], wz[4];
    int ix[4], iy[4];
    int i2 = atom_stencil(cell, pos, a, wx, wy, wz, ix, iy);
    float sum = 0.0f;
    int zlo = i2 - 1;
    if (zlo >= 0 && zlo <= 124) {
        int Q0 = zlo & ~3, off = zlo & 3;
        float q0[4] = {0,0,0,0}, q1[4] = {0,0,0,0};
        pad_quads(wz, off, q0, q1);
        #pragma unroll
        for (int i = 0; i < 4; i++) {
            float wi = wx[i];
            int ox = ix[i] << 14;
            #pragma unroll
            for (int j = 0; j < 4; j++) {
                const float* p = &d_rho[ox + (iy[j] << 7) + Q0];
                float4 v0 = __ldg((const float4*)p);
                float acc = v0.x*q0[0] + v0.y*q0[1] + v0.z*q0[2] + v0.w*q0[3];
                if (off) {
                    float4 v1 = __ldg((const float4*)(p + 4));
                    acc += v1.x*q1[0] + v1.y*q1[1] + v1.z*q1[2] + v1.w*q1[3];
                }
                sum += wi * wy[j] * acc;
            }
        }
    } else {
        int iz[4];
        #pragma unroll
        for (int s = 0; s < 4; s++) iz[s] = (zlo + s + 128) & 127;
        #pragma unroll
        for (int i = 0; i < 4; i++) {
            float wi = wx[i];
            int ox = ix[i] << 14;
            #pragma unroll
            for (int j = 0; j < 4; j++) {
                int oxy = ox + (iy[j] << 7);
                float acc = 0.0f;
                #pragma unroll
                for (int k = 0; k < 4; k++)
                    acc += wz[k] * d_rho[oxy + iz[k]];
                sum += wi * wy[j] * acc;
            }
        }
    }
    out[a] = sum - chg[a] * 0.7978845608028654f;
}

// ---------------------------------------------------------------------------
extern "C" void kernel_launch(void* const* d_in, const int* in_sizes, int n_in,
                              void* d_out, int out_size) {
    const float* cell = (const float*)d_in[0];
    const float* pos  = (const float*)d_in[1];
    const float* chg  = (const float*)d_in[2];
    float* out = (float*)d_out;
    int n = in_sizes[2];

    k_zero<<<2048, 256>>>();

    int ab = (n + 255) / 256;
    k_scatter<<<ab, 256>>>(cell, pos, chg, n);

    k_fft_z_fwd<<<1024, 256>>>();
    k_fft_y<0><<<1040, 256>>>();
    k_fft_x_gmul<<<1040, 256>>>(cell);
    k_fft_y<1><<<1040, 256>>>();
    k_fft_z_inv<<<1024, 256>>>();

    k_gather<<<ab, 256>>>(cell, pos, chg, out, n);
}